// round 1
// baseline (speedup 1.0000x reference)
#include <cuda_runtime.h>
#include <math.h>

#define N_NODES 50000
#define N_EDGES 800000
#define FDIM    128

// ---------------- static device scratch (no allocations allowed) ----------
__device__ int   g_deg[N_NODES];
__device__ int   g_cnt[N_NODES];
__device__ int   g_ofs[N_NODES];
__device__ int   g_rp[N_NODES + 1];
__device__ float g_dinv[N_NODES];
__device__ int   g_col[N_EDGES];
__device__ float g_wt[N_EDGES];
__device__ float g_T1[N_NODES * FDIM];
__device__ float g_T2[N_NODES * FDIM];
__device__ float g_T3[N_NODES * FDIM];
__device__ float g_T4[N_NODES * FDIM];
__device__ float g_H [N_NODES * FDIM];

// ---------------- preprocessing ----------------
__global__ void k_zero() {
    int i = blockIdx.x * blockDim.x + threadIdx.x;
    if (i < N_NODES) { g_deg[i] = 0; g_cnt[i] = 0; }
}

__global__ void k_count(const int* __restrict__ ei) {
    int e = blockIdx.x * blockDim.x + threadIdx.x;
    if (e < N_EDGES) {
        int s = ei[e], d = ei[N_EDGES + e];
        if (s != d) {
            atomicAdd(&g_deg[s], 1);
            atomicAdd(&g_cnt[d], 1);
        }
    }
}

__global__ void k_dinv() {
    int i = blockIdx.x * blockDim.x + threadIdx.x;
    if (i < N_NODES) {
        int dg = g_deg[i];
        g_dinv[i] = (dg > 0) ? rsqrtf((float)dg) : 0.0f;
    }
}

// single-block exclusive scan of g_cnt -> g_rp, g_ofs
__global__ void k_scan() {
    __shared__ int sh[1024];
    __shared__ int carry;
    int t = threadIdx.x;
    if (t == 0) carry = 0;
    __syncthreads();
    for (int base = 0; base < N_NODES; base += 1024) {
        int i = base + t;
        int v = (i < N_NODES) ? g_cnt[i] : 0;
        sh[t] = v;
        __syncthreads();
        #pragma unroll
        for (int off = 1; off < 1024; off <<= 1) {
            int u = (t >= off) ? sh[t - off] : 0;
            __syncthreads();
            sh[t] += u;
            __syncthreads();
        }
        if (i < N_NODES) {
            int ex = carry + sh[t] - v;
            g_rp[i]  = ex;
            g_ofs[i] = ex;
        }
        __syncthreads();
        if (t == 0) carry += sh[1023];
        __syncthreads();
    }
    if (t == 0) g_rp[N_NODES] = carry;
}

__global__ void k_fill(const int* __restrict__ ei) {
    int e = blockIdx.x * blockDim.x + threadIdx.x;
    if (e < N_EDGES) {
        int s = ei[e], d = ei[N_EDGES + e];
        if (s != d) {
            int p = atomicAdd(&g_ofs[d], 1);
            g_col[p] = s;
            g_wt[p]  = -g_dinv[s] * g_dinv[d];
        }
    }
}

// ---------------- SpMV: out = (cheb ? 2*L*vin - prev : L*vin) ------------
// one warp per dst row, each lane owns 4 consecutive features (float4)
__global__ void k_spmv(const float* __restrict__ vin,
                       const float* __restrict__ prev,
                       float* __restrict__ vout, int cheb) {
    int w    = (blockIdx.x * blockDim.x + threadIdx.x) >> 5;
    int lane = threadIdx.x & 31;
    if (w >= N_NODES) return;
    int beg = g_rp[w], end = g_rp[w + 1];

    float ax = 0.f, ay = 0.f, az = 0.f, aw = 0.f;
    const float4* vin4 = (const float4*)vin;
    int j = beg;
    for (; j + 1 < end; j += 2) {
        int   s0 = g_col[j],     s1 = g_col[j + 1];
        float w0 = g_wt[j],      w1 = g_wt[j + 1];
        float4 v0 = vin4[s0 * 32 + lane];
        float4 v1 = vin4[s1 * 32 + lane];
        ax += w0 * v0.x + w1 * v1.x;
        ay += w0 * v0.y + w1 * v1.y;
        az += w0 * v0.z + w1 * v1.z;
        aw += w0 * v0.w + w1 * v1.w;
    }
    if (j < end) {
        int   s0 = g_col[j];
        float w0 = g_wt[j];
        float4 v0 = vin4[s0 * 32 + lane];
        ax += w0 * v0.x; ay += w0 * v0.y; az += w0 * v0.z; aw += w0 * v0.w;
    }
    float4 r;
    if (cheb) {
        float4 p = ((const float4*)prev)[w * 32 + lane];
        r.x = 2.0f * ax - p.x;
        r.y = 2.0f * ay - p.y;
        r.z = 2.0f * az - p.z;
        r.w = 2.0f * aw - p.w;
    } else {
        r.x = ax; r.y = ay; r.z = az; r.w = aw;
    }
    ((float4*)vout)[w * 32 + lane] = r;
}

// ---------------- fused 5-slice GEMM: C = act(sum_k A_k @ B_k + bias) ----
struct A5 { const float* p[5]; };

template <bool RELU>
__global__ __launch_bounds__(256, 2)
void k_gemm(A5 A, const float* __restrict__ B,
            const float* __restrict__ bias, float* __restrict__ C) {
    __shared__ float As[16][132];   // [k][m], padded
    __shared__ float Bs[16][128];   // [k][n]

    const int tid = threadIdx.x;
    const int tx  = tid & 15;   // n-tile index
    const int ty  = tid >> 4;   // m-tile index
    const int m0  = blockIdx.x * 128;

    float acc[8][8];
    #pragma unroll
    for (int i = 0; i < 8; ++i)
        #pragma unroll
        for (int j = 0; j < 8; ++j) acc[i][j] = 0.f;

    for (int k = 0; k < 5; ++k) {
        const float* Ak = A.p[k];
        const float* Bk = B + k * 128 * 128;
        for (int kt = 0; kt < 128; kt += 16) {
            // A tile: 128 rows x 16 cols -> transposed As[k][m]
            #pragma unroll
            for (int i = 0; i < 2; ++i) {
                int f = tid + i * 256;        // 0..511
                int row = f >> 2, cv = f & 3;
                int gm = m0 + row;
                float4 v = make_float4(0.f, 0.f, 0.f, 0.f);
                if (gm < N_NODES)
                    v = *(const float4*)(Ak + (size_t)gm * 128 + kt + cv * 4);
                As[cv * 4 + 0][row] = v.x;
                As[cv * 4 + 1][row] = v.y;
                As[cv * 4 + 2][row] = v.z;
                As[cv * 4 + 3][row] = v.w;
            }
            // B tile: 16 x 128, direct
            #pragma unroll
            for (int i = 0; i < 2; ++i) {
                int f = tid + i * 256;
                int br = f >> 5, bc = f & 31;
                *(float4*)(&Bs[br][bc * 4]) =
                    *(const float4*)(Bk + (kt + br) * 128 + bc * 4);
            }
            __syncthreads();
            #pragma unroll
            for (int kk = 0; kk < 16; ++kk) {
                float a[8], b[8];
                *(float4*)(a)     = *(float4*)(&As[kk][ty * 8]);
                *(float4*)(a + 4) = *(float4*)(&As[kk][ty * 8 + 4]);
                *(float4*)(b)     = *(float4*)(&Bs[kk][tx * 8]);
                *(float4*)(b + 4) = *(float4*)(&Bs[kk][tx * 8 + 4]);
                #pragma unroll
                for (int i = 0; i < 8; ++i)
                    #pragma unroll
                    for (int j = 0; j < 8; ++j)
                        acc[i][j] += a[i] * b[j];
            }
            __syncthreads();
        }
    }
    // epilogue: bias (+ relu) + store
    #pragma unroll
    for (int i = 0; i < 8; ++i) {
        int gm = m0 + ty * 8 + i;
        if (gm >= N_NODES) continue;
        #pragma unroll
        for (int j = 0; j < 8; j += 4) {
            float4 r;
            r.x = acc[i][j + 0] + bias[tx * 8 + j + 0];
            r.y = acc[i][j + 1] + bias[tx * 8 + j + 1];
            r.z = acc[i][j + 2] + bias[tx * 8 + j + 2];
            r.w = acc[i][j + 3] + bias[tx * 8 + j + 3];
            if (RELU) {
                r.x = fmaxf(r.x, 0.f); r.y = fmaxf(r.y, 0.f);
                r.z = fmaxf(r.z, 0.f); r.w = fmaxf(r.w, 0.f);
            }
            *(float4*)(C + (size_t)gm * 128 + tx * 8 + j) = r;
        }
    }
}

// ---------------- head: out[n] = h[n,:] . Wl + bl ------------------------
__global__ void k_head(const float* __restrict__ H, const float* __restrict__ Wl,
                       const float* __restrict__ bl, float* __restrict__ out) {
    __shared__ float w[128];
    if (threadIdx.x < 128) w[threadIdx.x] = Wl[threadIdx.x];
    __syncthreads();
    int row  = blockIdx.x * 8 + (threadIdx.x >> 5);
    int lane = threadIdx.x & 31;
    if (row >= N_NODES) return;
    float4 h = ((const float4*)H)[row * 32 + lane];
    float s = h.x * w[lane * 4 + 0] + h.y * w[lane * 4 + 1] +
              h.z * w[lane * 4 + 2] + h.w * w[lane * 4 + 3];
    #pragma unroll
    for (int off = 16; off > 0; off >>= 1) s += __shfl_xor_sync(0xFFFFFFFFu, s, off);
    if (lane == 0) out[row] = s + bl[0];
}

// ---------------- launch --------------------------------------------------
extern "C" void kernel_launch(void* const* d_in, const int* in_sizes, int n_in,
                              void* d_out, int out_size) {
    const float* x  = (const float*)d_in[0];
    const int*   ei = (const int*)  d_in[1];
    const float* W0 = (const float*)d_in[2];
    const float* b0 = (const float*)d_in[3];
    const float* W1 = (const float*)d_in[4];
    const float* b1 = (const float*)d_in[5];
    const float* W2 = (const float*)d_in[6];
    const float* b2 = (const float*)d_in[7];
    const float* Wl = (const float*)d_in[8];
    const float* bl = (const float*)d_in[9];
    float* out = (float*)d_out;

    float *T1, *T2, *T3, *T4, *H;
    cudaGetSymbolAddress((void**)&T1, g_T1);
    cudaGetSymbolAddress((void**)&T2, g_T2);
    cudaGetSymbolAddress((void**)&T3, g_T3);
    cudaGetSymbolAddress((void**)&T4, g_T4);
    cudaGetSymbolAddress((void**)&H,  g_H);

    const int nb_n = (N_NODES + 255) / 256;
    const int nb_e = (N_EDGES + 255) / 256;
    const int spmv_blocks = (N_NODES * 32 + 255) / 256;
    const int gemm_blocks = (N_NODES + 127) / 128;

    // graph preprocessing -> CSR by dst
    k_zero <<<nb_n, 256>>>();
    k_count<<<nb_e, 256>>>(ei);
    k_dinv <<<nb_n, 256>>>();
    k_scan <<<1, 1024>>>();
    k_fill <<<nb_e, 256>>>(ei);

    // layer 0 (T0 = x)
    k_spmv<<<spmv_blocks, 256>>>(x,  nullptr, T1, 0);
    k_spmv<<<spmv_blocks, 256>>>(T1, x,       T2, 1);
    k_spmv<<<spmv_blocks, 256>>>(T2, T1,      T3, 1);
    k_spmv<<<spmv_blocks, 256>>>(T3, T2,      T4, 1);
    { A5 a; a.p[0]=x; a.p[1]=T1; a.p[2]=T2; a.p[3]=T3; a.p[4]=T4;
      k_gemm<true><<<gemm_blocks, 256>>>(a, W0, b0, H); }

    // layer 1 (T0 = H)
    k_spmv<<<spmv_blocks, 256>>>(H,  nullptr, T1, 0);
    k_spmv<<<spmv_blocks, 256>>>(T1, H,       T2, 1);
    k_spmv<<<spmv_blocks, 256>>>(T2, T1,      T3, 1);
    k_spmv<<<spmv_blocks, 256>>>(T3, T2,      T4, 1);
    { A5 a; a.p[0]=H; a.p[1]=T1; a.p[2]=T2; a.p[3]=T3; a.p[4]=T4;
      k_gemm<true><<<gemm_blocks, 256>>>(a, W1, b1, H); }   // in-place safe

    // layer 2 (no relu)
    k_spmv<<<spmv_blocks, 256>>>(H,  nullptr, T1, 0);
    k_spmv<<<spmv_blocks, 256>>>(T1, H,       T2, 1);
    k_spmv<<<spmv_blocks, 256>>>(T2, T1,      T3, 1);
    k_spmv<<<spmv_blocks, 256>>>(T3, T2,      T4, 1);
    { A5 a; a.p[0]=H; a.p[1]=T1; a.p[2]=T2; a.p[3]=T3; a.p[4]=T4;
      k_gemm<false><<<gemm_blocks, 256>>>(a, W2, b2, H); }  // in-place safe

    // linear head
    k_head<<<(N_NODES + 7) / 8, 256>>>(H, Wl, bl, out);
}

// round 2
// speedup vs baseline: 1.4031x; 1.4031x over previous
#include <cuda_runtime.h>
#include <math.h>

#define N_NODES 50000
#define N_EDGES 800000
#define FDIM    128
#define SCAN_B  ((N_NODES + 1023) / 1024)

// ---------------- static device scratch (no allocations allowed) ----------
__device__ int   g_deg[N_NODES];
__device__ int   g_cnt[N_NODES];
__device__ int   g_ofs[N_NODES];
__device__ int   g_rp[N_NODES + 1];
__device__ float g_dinv[N_NODES];
__device__ int   g_col[N_EDGES];
__device__ float g_wt[N_EDGES];
__device__ int   g_bsum[SCAN_B];
__device__ int   g_bofs[SCAN_B];
__device__ float g_T1[N_NODES * FDIM];
__device__ float g_T2[N_NODES * FDIM];
__device__ float g_T3[N_NODES * FDIM];
__device__ float g_T4[N_NODES * FDIM];
__device__ float g_H [N_NODES * FDIM];
__device__ float g_C2[5 * FDIM];   // folded W2[k] @ Wl
__device__ float g_c0[1];          // b2 . Wl + bl

// ---------------- f32x2 packed helpers (Blackwell FFMA2) ------------------
typedef unsigned long long ull;
__device__ __forceinline__ ull pk2(float x, float y) {
    ull r; asm("mov.b64 %0,{%1,%2};" : "=l"(r) : "f"(x), "f"(y)); return r;
}
__device__ __forceinline__ void upk2(ull v, float& x, float& y) {
    asm("mov.b64 {%0,%1},%2;" : "=f"(x), "=f"(y) : "l"(v));
}
__device__ __forceinline__ void fma2(ull& d, ull a, ull b) {
    asm("fma.rn.f32x2 %0,%1,%2,%0;" : "+l"(d) : "l"(a), "l"(b));
}

// ---------------- preprocessing ----------------
__global__ void k_zero() {
    int i = blockIdx.x * blockDim.x + threadIdx.x;
    if (i < N_NODES) { g_deg[i] = 0; g_cnt[i] = 0; }
}

__global__ void k_count(const int* __restrict__ ei) {
    int e = blockIdx.x * blockDim.x + threadIdx.x;
    if (e < N_EDGES) {
        int s = ei[e], d = ei[N_EDGES + e];
        if (s != d) {
            atomicAdd(&g_deg[s], 1);
            atomicAdd(&g_cnt[d], 1);
        }
    }
}

__global__ void k_dinv() {
    int i = blockIdx.x * blockDim.x + threadIdx.x;
    if (i < N_NODES) {
        int dg = g_deg[i];
        g_dinv[i] = (dg > 0) ? rsqrtf((float)dg) : 0.0f;
    }
}

// multi-block scan, pass A: per-block exclusive scan + block sums
__global__ void k_scanA() {
    __shared__ int wsum[32];
    int tid  = threadIdx.x;
    int lane = tid & 31, wid = tid >> 5;
    int i = blockIdx.x * 1024 + tid;
    int v = (i < N_NODES) ? g_cnt[i] : 0;
    int x = v;
    #pragma unroll
    for (int off = 1; off < 32; off <<= 1) {
        int y = __shfl_up_sync(0xFFFFFFFFu, x, off);
        if (lane >= off) x += y;
    }
    if (lane == 31) wsum[wid] = x;
    __syncthreads();
    if (wid == 0) {
        int y = wsum[lane];
        #pragma unroll
        for (int off = 1; off < 32; off <<= 1) {
            int z = __shfl_up_sync(0xFFFFFFFFu, y, off);
            if (lane >= off) y += z;
        }
        wsum[lane] = y;
    }
    __syncthreads();
    int excl = x - v + (wid > 0 ? wsum[wid - 1] : 0);
    if (i < N_NODES) g_rp[i] = excl;
    if (tid == 0) g_bsum[blockIdx.x] = wsum[31];
}

// pass B: serial scan of block sums (tiny)
__global__ void k_scanB() {
    int run = 0;
    for (int b = 0; b < SCAN_B; ++b) {
        g_bofs[b] = run;
        run += g_bsum[b];
    }
    g_rp[N_NODES] = run;
}

// pass C: add block offsets
__global__ void k_scanC() {
    int i = blockIdx.x * 1024 + threadIdx.x;
    if (i < N_NODES) {
        int r = g_rp[i] + g_bofs[blockIdx.x];
        g_rp[i]  = r;
        g_ofs[i] = r;
    }
}

__global__ void k_fill(const int* __restrict__ ei) {
    int e = blockIdx.x * blockDim.x + threadIdx.x;
    if (e < N_EDGES) {
        int s = ei[e], d = ei[N_EDGES + e];
        if (s != d) {
            int p = atomicAdd(&g_ofs[d], 1);
            g_col[p] = s;
            g_wt[p]  = -g_dinv[s] * g_dinv[d];
        }
    }
}

// fold W2[k] @ Wl -> g_C2, and b2.Wl + bl -> g_c0
__global__ void k_fold(const float* __restrict__ W2, const float* __restrict__ b2,
                       const float* __restrict__ Wl, const float* __restrict__ bl) {
    int k = blockIdx.x;      // 0..4
    int f = threadIdx.x;     // 0..127
    const float* row = W2 + ((size_t)k * 128 + f) * 128;
    float s = 0.f;
    #pragma unroll 4
    for (int w = 0; w < 128; ++w) s += row[w] * Wl[w];
    g_C2[k * 128 + f] = s;
    if (k == 0 && f == 0) {
        float c = bl[0];
        for (int w = 0; w < 128; ++w) c += b2[w] * Wl[w];
        g_c0[0] = c;
    }
}

// ---------------- SpMV: out = (cheb ? 2*L*vin - prev : L*vin) ------------
__global__ void k_spmv(const float* __restrict__ vin,
                       const float* __restrict__ prev,
                       float* __restrict__ vout, int cheb) {
    int w    = (blockIdx.x * blockDim.x + threadIdx.x) >> 5;
    int lane = threadIdx.x & 31;
    if (w >= N_NODES) return;
    int beg = g_rp[w], end = g_rp[w + 1];

    float ax = 0.f, ay = 0.f, az = 0.f, aw = 0.f;
    const float4* vin4 = (const float4*)vin;
    int j = beg;
    for (; j + 1 < end; j += 2) {
        int   s0 = g_col[j],     s1 = g_col[j + 1];
        float w0 = g_wt[j],      w1 = g_wt[j + 1];
        float4 v0 = vin4[s0 * 32 + lane];
        float4 v1 = vin4[s1 * 32 + lane];
        ax += w0 * v0.x + w1 * v1.x;
        ay += w0 * v0.y + w1 * v1.y;
        az += w0 * v0.z + w1 * v1.z;
        aw += w0 * v0.w + w1 * v1.w;
    }
    if (j < end) {
        int   s0 = g_col[j];
        float w0 = g_wt[j];
        float4 v0 = vin4[s0 * 32 + lane];
        ax += w0 * v0.x; ay += w0 * v0.y; az += w0 * v0.z; aw += w0 * v0.w;
    }
    float4 r;
    if (cheb) {
        float4 p = ((const float4*)prev)[w * 32 + lane];
        r.x = 2.0f * ax - p.x;
        r.y = 2.0f * ay - p.y;
        r.z = 2.0f * az - p.z;
        r.w = 2.0f * aw - p.w;
    } else {
        r.x = ax; r.y = ay; r.z = az; r.w = aw;
    }
    ((float4*)vout)[w * 32 + lane] = r;
}

// ---------------- fused 5-slice GEMM with packed f32x2 accumulators ------
struct A5 { const float* p[5]; };

template <bool RELU>
__global__ __launch_bounds__(256, 2)
void k_gemm(A5 A, const float* __restrict__ B,
            const float* __restrict__ bias, float* __restrict__ C) {
    __shared__ float As[16][132];   // [k][m], padded, 16B-aligned rows (132*4=528)
    __shared__ float Bs[16][128];   // [k][n]

    const int tid = threadIdx.x;
    const int tx  = tid & 15;   // n-tile index
    const int ty  = tid >> 4;   // m-tile index
    const int m0  = blockIdx.x * 128;

    // acc packed along M: accp[ii][j] = (acc[2ii][j], acc[2ii+1][j])
    ull accp[4][8];
    #pragma unroll
    for (int ii = 0; ii < 4; ++ii)
        #pragma unroll
        for (int j = 0; j < 8; ++j) accp[ii][j] = 0ull;

    for (int k = 0; k < 5; ++k) {
        const float* Ak = A.p[k];
        const float* Bk = B + k * 128 * 128;
        for (int kt = 0; kt < 128; kt += 16) {
            #pragma unroll
            for (int i = 0; i < 2; ++i) {
                int f = tid + i * 256;        // 0..511
                int row = f >> 2, cv = f & 3;
                int gm = m0 + row;
                float4 v = make_float4(0.f, 0.f, 0.f, 0.f);
                if (gm < N_NODES)
                    v = *(const float4*)(Ak + (size_t)gm * 128 + kt + cv * 4);
                As[cv * 4 + 0][row] = v.x;
                As[cv * 4 + 1][row] = v.y;
                As[cv * 4 + 2][row] = v.z;
                As[cv * 4 + 3][row] = v.w;
            }
            #pragma unroll
            for (int i = 0; i < 2; ++i) {
                int f = tid + i * 256;
                int br = f >> 5, bc = f & 31;
                *(float4*)(&Bs[br][bc * 4]) =
                    *(const float4*)(Bk + (kt + br) * 128 + bc * 4);
            }
            __syncthreads();
            #pragma unroll
            for (int kk = 0; kk < 16; ++kk) {
                // a-pairs come directly as 64-bit lanes from LDS.128
                ulonglong2 a01 = *(const ulonglong2*)&As[kk][ty * 8];
                ulonglong2 a23 = *(const ulonglong2*)&As[kk][ty * 8 + 4];
                ull ap[4] = { a01.x, a01.y, a23.x, a23.y };
                float b[8];
                *(float4*)(b)     = *(float4*)(&Bs[kk][tx * 8]);
                *(float4*)(b + 4) = *(float4*)(&Bs[kk][tx * 8 + 4]);
                ull bb[8];
                #pragma unroll
                for (int j = 0; j < 8; ++j) bb[j] = pk2(b[j], b[j]);
                #pragma unroll
                for (int ii = 0; ii < 4; ++ii)
                    #pragma unroll
                    for (int j = 0; j < 8; ++j)
                        fma2(accp[ii][j], ap[ii], bb[j]);
            }
            __syncthreads();
        }
    }
    // epilogue: unpack, bias (+ relu), store
    #pragma unroll
    for (int ii = 0; ii < 4; ++ii) {
        float r0[8], r1[8];
        #pragma unroll
        for (int j = 0; j < 8; ++j) upk2(accp[ii][j], r0[j], r1[j]);
        #pragma unroll
        for (int h = 0; h < 2; ++h) {
            float* rr = h ? r1 : r0;
            int gm = m0 + ty * 8 + 2 * ii + h;
            if (gm >= N_NODES) continue;
            #pragma unroll
            for (int j = 0; j < 8; j += 4) {
                float4 r;
                r.x = rr[j + 0] + bias[tx * 8 + j + 0];
                r.y = rr[j + 1] + bias[tx * 8 + j + 1];
                r.z = rr[j + 2] + bias[tx * 8 + j + 2];
                r.w = rr[j + 3] + bias[tx * 8 + j + 3];
                if (RELU) {
                    r.x = fmaxf(r.x, 0.f); r.y = fmaxf(r.y, 0.f);
                    r.z = fmaxf(r.z, 0.f); r.w = fmaxf(r.w, 0.f);
                }
                *(float4*)(C + (size_t)gm * 128 + tx * 8 + j) = r;
            }
        }
    }
}

// ---------------- fused layer-2 + head: out[n] = sum_k T_k[n,:].C2[k] + c0
__global__ void k_out(A5 T, float* __restrict__ out) {
    __shared__ float c2[5 * 128];
    for (int i = threadIdx.x; i < 5 * 128; i += blockDim.x) c2[i] = g_C2[i];
    __syncthreads();
    int row  = blockIdx.x * 8 + (threadIdx.x >> 5);
    int lane = threadIdx.x & 31;
    if (row >= N_NODES) return;
    float s = 0.f;
    #pragma unroll
    for (int k = 0; k < 5; ++k) {
        float4 h = ((const float4*)T.p[k])[row * 32 + lane];
        const float* w = c2 + k * 128 + lane * 4;
        s += h.x * w[0] + h.y * w[1] + h.z * w[2] + h.w * w[3];
    }
    #pragma unroll
    for (int off = 16; off > 0; off >>= 1) s += __shfl_xor_sync(0xFFFFFFFFu, s, off);
    if (lane == 0) out[row] = s + g_c0[0];
}

// ---------------- launch --------------------------------------------------
extern "C" void kernel_launch(void* const* d_in, const int* in_sizes, int n_in,
                              void* d_out, int out_size) {
    const float* x  = (const float*)d_in[0];
    const int*   ei = (const int*)  d_in[1];
    const float* W0 = (const float*)d_in[2];
    const float* b0 = (const float*)d_in[3];
    const float* W1 = (const float*)d_in[4];
    const float* b1 = (const float*)d_in[5];
    const float* W2 = (const float*)d_in[6];
    const float* b2 = (const float*)d_in[7];
    const float* Wl = (const float*)d_in[8];
    const float* bl = (const float*)d_in[9];
    float* out = (float*)d_out;

    float *T1, *T2, *T3, *T4, *H;
    cudaGetSymbolAddress((void**)&T1, g_T1);
    cudaGetSymbolAddress((void**)&T2, g_T2);
    cudaGetSymbolAddress((void**)&T3, g_T3);
    cudaGetSymbolAddress((void**)&T4, g_T4);
    cudaGetSymbolAddress((void**)&H,  g_H);

    const int nb_n = (N_NODES + 255) / 256;
    const int nb_e = (N_EDGES + 255) / 256;
    const int spmv_blocks = (N_NODES * 32 + 255) / 256;
    const int gemm_blocks = (N_NODES + 127) / 128;

    // graph preprocessing -> CSR by dst
    k_zero <<<nb_n, 256>>>();
    k_count<<<nb_e, 256>>>(ei);
    k_dinv <<<nb_n, 256>>>();
    k_scanA<<<SCAN_B, 1024>>>();
    k_scanB<<<1, 1>>>();
    k_scanC<<<SCAN_B, 1024>>>();
    k_fill <<<nb_e, 256>>>(ei);
    k_fold <<<5, 128>>>(W2, b2, Wl, bl);

    // layer 0 (T0 = x)
    k_spmv<<<spmv_blocks, 256>>>(x,  nullptr, T1, 0);
    k_spmv<<<spmv_blocks, 256>>>(T1, x,       T2, 1);
    k_spmv<<<spmv_blocks, 256>>>(T2, T1,      T3, 1);
    k_spmv<<<spmv_blocks, 256>>>(T3, T2,      T4, 1);
    { A5 a; a.p[0]=x; a.p[1]=T1; a.p[2]=T2; a.p[3]=T3; a.p[4]=T4;
      k_gemm<true><<<gemm_blocks, 256>>>(a, W0, b0, H); }

    // layer 1 (T0 = H)
    k_spmv<<<spmv_blocks, 256>>>(H,  nullptr, T1, 0);
    k_spmv<<<spmv_blocks, 256>>>(T1, H,       T2, 1);
    k_spmv<<<spmv_blocks, 256>>>(T2, T1,      T3, 1);
    k_spmv<<<spmv_blocks, 256>>>(T3, T2,      T4, 1);
    { A5 a; a.p[0]=H; a.p[1]=T1; a.p[2]=T2; a.p[3]=T3; a.p[4]=T4;
      k_gemm<true><<<gemm_blocks, 256>>>(a, W1, b1, H); }   // in-place safe

    // layer 2 folded into head: out = sum_k T_k @ C2[k] + c0
    k_spmv<<<spmv_blocks, 256>>>(H,  nullptr, T1, 0);
    k_spmv<<<spmv_blocks, 256>>>(T1, H,       T2, 1);
    k_spmv<<<spmv_blocks, 256>>>(T2, T1,      T3, 1);
    k_spmv<<<spmv_blocks, 256>>>(T3, T2,      T4, 1);
    { A5 t; t.p[0]=H; t.p[1]=T1; t.p[2]=T2; t.p[3]=T3; t.p[4]=T4;
      k_out<<<(N_NODES + 7) / 8, 256>>>(t, out); }
}

// round 5
// speedup vs baseline: 1.4078x; 1.0034x over previous
#include <cuda_runtime.h>
#include <cstdint>
#include <math.h>

#define N_NODES 50000
#define N_EDGES 800000
#define FDIM    128
#define SCAN_B  ((N_NODES + 1023) / 1024)
#define GEMM_BLKS (((N_NODES + 127) / 128) * 2)   // 782 (128-row x 64-col tiles)
#define SPMV_BLKS ((N_NODES * 32 + 255) / 256)    // 6250

// ---------------- static device scratch ----------------
__device__ int   g_deg[N_NODES];
__device__ int   g_cnt[N_NODES];
__device__ int   g_ofs[N_NODES];
__device__ int   g_rp[N_NODES + 1];
__device__ float g_dinv[N_NODES];
__device__ int   g_col[N_EDGES];
__device__ float g_wt[N_EDGES];
__device__ int   g_bsum[SCAN_B];
__device__ int   g_bofs[SCAN_B];
__device__ float g_T1[N_NODES * FDIM];
__device__ float g_T2[N_NODES * FDIM];
__device__ float g_T3[N_NODES * FDIM];
__device__ float g_T4[N_NODES * FDIM];
__device__ float g_H [N_NODES * FDIM];
__device__ float g_H2[N_NODES * FDIM];
__device__ float g_C2[5 * FDIM];
__device__ float g_c0[1];

// ---------------- f32x2 packed helpers ----------------
typedef unsigned long long ull;
__device__ __forceinline__ ull pk2(float x, float y) {
    ull r; asm("mov.b64 %0,{%1,%2};" : "=l"(r) : "f"(x), "f"(y)); return r;
}
__device__ __forceinline__ void upk2(ull v, float& x, float& y) {
    asm("mov.b64 {%0,%1},%2;" : "=f"(x), "=f"(y) : "l"(v));
}
__device__ __forceinline__ void fma2(ull& d, ull a, ull b) {
    asm("fma.rn.f32x2 %0,%1,%2,%0;" : "+l"(d) : "l"(a), "l"(b));
}

// ---------------- preprocessing ----------------
__global__ void k_zero() {
    int i = blockIdx.x * blockDim.x + threadIdx.x;
    if (i < N_NODES) { g_deg[i] = 0; g_cnt[i] = 0; }
}

__global__ void k_count(const int* __restrict__ ei) {
    int e = blockIdx.x * blockDim.x + threadIdx.x;
    if (e < N_EDGES) {
        int s = ei[e], d = ei[N_EDGES + e];
        if (s != d) {
            atomicAdd(&g_deg[s], 1);
            atomicAdd(&g_cnt[d], 1);
        }
    }
}

__global__ void k_dinv() {
    int i = blockIdx.x * blockDim.x + threadIdx.x;
    if (i < N_NODES) {
        int dg = g_deg[i];
        g_dinv[i] = (dg > 0) ? rsqrtf((float)dg) : 0.0f;
    }
}

__global__ void k_scanA() {
    __shared__ int wsum[32];
    int tid  = threadIdx.x;
    int lane = tid & 31, wid = tid >> 5;
    int i = blockIdx.x * 1024 + tid;
    int v = (i < N_NODES) ? g_cnt[i] : 0;
    int x = v;
    #pragma unroll
    for (int off = 1; off < 32; off <<= 1) {
        int y = __shfl_up_sync(0xFFFFFFFFu, x, off);
        if (lane >= off) x += y;
    }
    if (lane == 31) wsum[wid] = x;
    __syncthreads();
    if (wid == 0) {
        int y = wsum[lane];
        #pragma unroll
        for (int off = 1; off < 32; off <<= 1) {
            int z = __shfl_up_sync(0xFFFFFFFFu, y, off);
            if (lane >= off) y += z;
        }
        wsum[lane] = y;
    }
    __syncthreads();
    int excl = x - v + (wid > 0 ? wsum[wid - 1] : 0);
    if (i < N_NODES) g_rp[i] = excl;
    if (tid == 0) g_bsum[blockIdx.x] = wsum[31];
}

__global__ void k_scanB() {
    int run = 0;
    for (int b = 0; b < SCAN_B; ++b) {
        g_bofs[b] = run;
        run += g_bsum[b];
    }
    g_rp[N_NODES] = run;
}

__global__ void k_scanC() {
    int i = blockIdx.x * 1024 + threadIdx.x;
    if (i < N_NODES) {
        int r = g_rp[i] + g_bofs[blockIdx.x];
        g_rp[i]  = r;
        g_ofs[i] = r;
    }
}

__global__ void k_fill(const int* __restrict__ ei) {
    int e = blockIdx.x * blockDim.x + threadIdx.x;
    if (e < N_EDGES) {
        int s = ei[e], d = ei[N_EDGES + e];
        if (s != d) {
            int p = atomicAdd(&g_ofs[d], 1);
            g_col[p] = s;
            g_wt[p]  = -g_dinv[s] * g_dinv[d];
        }
    }
}

__global__ void k_fold(const float* __restrict__ W2, const float* __restrict__ b2,
                       const float* __restrict__ Wl, const float* __restrict__ bl) {
    int k = blockIdx.x;
    int f = threadIdx.x;
    const float* row = W2 + ((size_t)k * 128 + f) * 128;
    float s = 0.f;
    #pragma unroll 4
    for (int w = 0; w < 128; ++w) s += row[w] * Wl[w];
    g_C2[k * 128 + f] = s;
    if (k == 0 && f == 0) {
        float c = bl[0];
        for (int w = 0; w < 128; ++w) c += b2[w] * Wl[w];
        g_c0[0] = c;
    }
}

// ---------------- device: SpMV for one row-warp ----------------
__device__ __forceinline__ void spmv_body(
    int w, int lane,
    const float* __restrict__ vin, const float* __restrict__ prev,
    float* __restrict__ vout, int cheb)
{
    int beg = g_rp[w], end = g_rp[w + 1];
    float ax = 0.f, ay = 0.f, az = 0.f, aw = 0.f;
    const float4* vin4 = (const float4*)vin;
    int j = beg;
    for (; j + 1 < end; j += 2) {
        int   s0 = g_col[j],     s1 = g_col[j + 1];
        float w0 = g_wt[j],      w1 = g_wt[j + 1];
        float4 v0 = vin4[s0 * 32 + lane];
        float4 v1 = vin4[s1 * 32 + lane];
        ax += w0 * v0.x + w1 * v1.x;
        ay += w0 * v0.y + w1 * v1.y;
        az += w0 * v0.z + w1 * v1.z;
        aw += w0 * v0.w + w1 * v1.w;
    }
    if (j < end) {
        int   s0 = g_col[j];
        float w0 = g_wt[j];
        float4 v0 = vin4[s0 * 32 + lane];
        ax += w0 * v0.x; ay += w0 * v0.y; az += w0 * v0.z; aw += w0 * v0.w;
    }
    float4 r;
    if (cheb) {
        float4 p = ((const float4*)prev)[w * 32 + lane];
        r.x = 2.0f * ax - p.x;
        r.y = 2.0f * ay - p.y;
        r.z = 2.0f * az - p.z;
        r.w = 2.0f * aw - p.w;
    } else {
        r.x = ax; r.y = ay; r.z = az; r.w = aw;
    }
    ((float4*)vout)[w * 32 + lane] = r;
}

// ---------------- fat kernel: GEMM-slice blocks + SpMV blocks ------------
// blocks [0, nGemm)           : C[128x64 tile] (+)= Ak[128x128] @ Bk[128x128][:,n0:n0+64]
// blocks [nGemm, nGemm+spmv)  : one warp per dst row matvec
__global__ __launch_bounds__(256, 3)
void k_fat(const float* __restrict__ vin, const float* __restrict__ prev,
           float* __restrict__ vout, int cheb,
           const float* __restrict__ Ak, const float* __restrict__ Bk,
           const float* __restrict__ bias, float* __restrict__ C,
           int first, int last, int relu, int nGemm)
{
    __shared__ float As[16][132];
    __shared__ float Bs[16][68];

    const int bid = blockIdx.x;
    const int tid = threadIdx.x;

    if (bid >= nGemm) {
        int w = ((bid - nGemm) * 256 + tid) >> 5;
        if (w < N_NODES) spmv_body(w, tid & 31, vin, prev, vout, cheb);
        return;
    }

    // ---------------- GEMM slice ----------------
    const int mblk = bid >> 1;
    const int n0   = (bid & 1) * 64;
    const int m0   = mblk * 128;
    const int tx   = tid & 15;   // n: 4 cols each
    const int ty   = tid >> 4;   // m: 8 rows each

    ull accp[4][4];
    #pragma unroll
    for (int ii = 0; ii < 4; ++ii)
        #pragma unroll
        for (int j = 0; j < 4; ++j) accp[ii][j] = 0ull;

    for (int kt = 0; kt < 128; kt += 16) {
        // A tile: 128 rows x 16 k, transposed As[k][m]
        #pragma unroll
        for (int i = 0; i < 2; ++i) {
            int f = tid + i * 256;        // 0..511
            int row = f >> 2, cv = f & 3;
            int gm = m0 + row;
            float4 v = make_float4(0.f, 0.f, 0.f, 0.f);
            if (gm < N_NODES)
                v = *(const float4*)(Ak + (size_t)gm * 128 + kt + cv * 4);
            As[cv * 4 + 0][row] = v.x;
            As[cv * 4 + 1][row] = v.y;
            As[cv * 4 + 2][row] = v.z;
            As[cv * 4 + 3][row] = v.w;
        }
        // B tile: 16 k x 64 n
        {
            int br = tid >> 4, bc = tid & 15;
            *(float4*)(&Bs[br][bc * 4]) =
                *(const float4*)(Bk + (kt + br) * 128 + n0 + bc * 4);
        }
        __syncthreads();
        #pragma unroll
        for (int kk = 0; kk < 16; ++kk) {
            ulonglong2 a01 = *(const ulonglong2*)&As[kk][ty * 8];
            ulonglong2 a23 = *(const ulonglong2*)&As[kk][ty * 8 + 4];
            ull ap[4] = { a01.x, a01.y, a23.x, a23.y };
            float4 bv = *(float4*)(&Bs[kk][tx * 4]);
            ull bb[4] = { pk2(bv.x, bv.x), pk2(bv.y, bv.y),
                          pk2(bv.z, bv.z), pk2(bv.w, bv.w) };
            #pragma unroll
            for (int ii = 0; ii < 4; ++ii)
                #pragma unroll
                for (int j = 0; j < 4; ++j)
                    fma2(accp[ii][j], ap[ii], bb[j]);
        }
        __syncthreads();
    }

    // epilogue: (+)= into C, bias/relu on last slice
    float4 bset = make_float4(0.f, 0.f, 0.f, 0.f);
    if (last) bset = *(const float4*)(bias + n0 + tx * 4);
    #pragma unroll
    for (int ii = 0; ii < 4; ++ii) {
        float r0[4], r1[4];
        #pragma unroll
        for (int j = 0; j < 4; ++j) upk2(accp[ii][j], r0[j], r1[j]);
        #pragma unroll
        for (int h = 0; h < 2; ++h) {
            float* rr = h ? r1 : r0;
            int gm = m0 + ty * 8 + 2 * ii + h;
            if (gm >= N_NODES) continue;
            float* cp = C + (size_t)gm * 128 + n0 + tx * 4;
            float4 o;
            o.x = rr[0]; o.y = rr[1]; o.z = rr[2]; o.w = rr[3];
            if (!first) {
                float4 old = *(float4*)cp;
                o.x += old.x; o.y += old.y; o.z += old.z; o.w += old.w;
            }
            if (last) {
                o.x += bset.x; o.y += bset.y; o.z += bset.z; o.w += bset.w;
                if (relu) {
                    o.x = fmaxf(o.x, 0.f); o.y = fmaxf(o.y, 0.f);
                    o.z = fmaxf(o.z, 0.f); o.w = fmaxf(o.w, 0.f);
                }
            }
            *(float4*)cp = o;
        }
    }
}

// ---------------- fused layer-2 + head ----------------
struct A5 { const float* p[5]; };

__global__ void k_out(A5 T, float* __restrict__ out) {
    __shared__ float c2[5 * 128];
    for (int i = threadIdx.x; i < 5 * 128; i += blockDim.x) c2[i] = g_C2[i];
    __syncthreads();
    int row  = blockIdx.x * 8 + (threadIdx.x >> 5);
    int lane = threadIdx.x & 31;
    if (row >= N_NODES) return;
    float s = 0.f;
    #pragma unroll
    for (int k = 0; k < 5; ++k) {
        float4 h = ((const float4*)T.p[k])[row * 32 + lane];
        const float* w = c2 + k * 128 + lane * 4;
        s += h.x * w[0] + h.y * w[1] + h.z * w[2] + h.w * w[3];
    }
    #pragma unroll
    for (int off = 16; off > 0; off >>= 1) s += __shfl_xor_sync(0xFFFFFFFFu, s, off);
    if (lane == 0) out[row] = s + g_c0[0];
}

// ---------------- launch --------------------------------------------------
extern "C" void kernel_launch(void* const* d_in, const int* in_sizes, int n_in,
                              void* d_out, int out_size) {
    const float* x  = (const float*)d_in[0];
    const int*   ei = (const int*)  d_in[1];
    const float* W0 = (const float*)d_in[2];
    const float* b0 = (const float*)d_in[3];
    const float* W1 = (const float*)d_in[4];
    const float* b1 = (const float*)d_in[5];
    const float* W2 = (const float*)d_in[6];
    const float* b2 = (const float*)d_in[7];
    const float* Wl = (const float*)d_in[8];
    const float* bl = (const float*)d_in[9];
    float* out = (float*)d_out;

    float *T1, *T2, *T3, *T4, *H, *H2;
    cudaGetSymbolAddress((void**)&T1, g_T1);
    cudaGetSymbolAddress((void**)&T2, g_T2);
    cudaGetSymbolAddress((void**)&T3, g_T3);
    cudaGetSymbolAddress((void**)&T4, g_T4);
    cudaGetSymbolAddress((void**)&H,  g_H);
    cudaGetSymbolAddress((void**)&H2, g_H2);

    const int nb_n = (N_NODES + 255) / 256;
    const int nb_e = (N_EDGES + 255) / 256;
    const int FAT  = GEMM_BLKS + SPMV_BLKS;
    const size_t KS = 128 * 128;   // one weight slice

    k_zero <<<nb_n, 256>>>();
    k_count<<<nb_e, 256>>>(ei);
    k_dinv <<<nb_n, 256>>>();
    k_scanA<<<SCAN_B, 1024>>>();
    k_scanB<<<1, 1>>>();
    k_scanC<<<SCAN_B, 1024>>>();
    k_fill <<<nb_e, 256>>>(ei);
    k_fold <<<5, 128>>>(W2, b2, Wl, bl);

    // ---- layer 0 (T0 = x, C = H) : overlap gemm slice k with matvec k+1 ----
    k_fat<<<FAT, 256>>>(x,  nullptr, T1, 0,  x,  W0 + 0*KS, b0, H, 1, 0, 0, GEMM_BLKS);
    k_fat<<<FAT, 256>>>(T1, x,       T2, 1,  T1, W0 + 1*KS, b0, H, 0, 0, 0, GEMM_BLKS);
    k_fat<<<FAT, 256>>>(T2, T1,      T3, 1,  T2, W0 + 2*KS, b0, H, 0, 0, 0, GEMM_BLKS);
    k_fat<<<FAT, 256>>>(T3, T2,      T4, 1,  T3, W0 + 3*KS, b0, H, 0, 0, 0, GEMM_BLKS);
    k_fat<<<GEMM_BLKS, 256>>>(nullptr, nullptr, nullptr, 0,
                              T4, W0 + 4*KS, b0, H, 0, 1, 1, GEMM_BLKS);

    // ---- layer 1 (T0 = H, C = H2) ----
    k_fat<<<FAT, 256>>>(H,  nullptr, T1, 0,  H,  W1 + 0*KS, b1, H2, 1, 0, 0, GEMM_BLKS);
    k_fat<<<FAT, 256>>>(T1, H,       T2, 1,  T1, W1 + 1*KS, b1, H2, 0, 0, 0, GEMM_BLKS);
    k_fat<<<FAT, 256>>>(T2, T1,      T3, 1,  T2, W1 + 2*KS, b1, H2, 0, 0, 0, GEMM_BLKS);
    k_fat<<<FAT, 256>>>(T3, T2,      T4, 1,  T3, W1 + 3*KS, b1, H2, 0, 0, 0, GEMM_BLKS);
    k_fat<<<GEMM_BLKS, 256>>>(nullptr, nullptr, nullptr, 0,
                              T4, W1 + 4*KS, b1, H2, 0, 1, 1, GEMM_BLKS);

    // ---- layer 2 (T0 = H2), GEMM folded into head ----
    k_fat<<<SPMV_BLKS, 256>>>(H2, nullptr, T1, 0,
                              nullptr, nullptr, nullptr, nullptr, 0, 0, 0, 0);
    k_fat<<<SPMV_BLKS, 256>>>(T1, H2,      T2, 1,
                              nullptr, nullptr, nullptr, nullptr, 0, 0, 0, 0);
    k_fat<<<SPMV_BLKS, 256>>>(T2, T1,      T3, 1,
                              nullptr, nullptr, nullptr, nullptr, 0, 0, 0, 0);
    k_fat<<<SPMV_BLKS, 256>>>(T3, T2,      T4, 1,
                              nullptr, nullptr, nullptr, nullptr, 0, 0, 0, 0);

    { A5 t; t.p[0]=H2; t.p[1]=T1; t.p[2]=T2; t.p[3]=T3; t.p[4]=T4;
      k_out<<<(N_NODES + 7) / 8, 256>>>(t, out); }
}